// round 6
// baseline (speedup 1.0000x reference)
#include <cuda_runtime.h>

// ---------------------------------------------------------------------------
// Fused NeRF MLP evaluation, fp32, f32x2-packed FFMA.
// One CTA = 128 points. Activations live in SMEM feature-major: act[f][r],
// f in [0,328), r in [0,128). Concats become contiguous column ranges:
//   pe_x    -> cols [0,63)
//   features-> cols [63,319)        (in-place updated every layer)
//   pe_d    -> cols [24,63)         (written after g2 layer0 consumed pe_x)
// Columns [319,328) stay zero so K-tail reads (K=63/319/295, tiles of 8)
// multiply garbage-free zeros.
// ---------------------------------------------------------------------------

#define TPB    512
#define MROWS  128
#define AST    128          // act row stride (floats)
#define ACOLS  328
#define WS_OFF  (ACOLS*AST)          // 41984 floats
#define BS_OFF  (WS_OFF + 4096)      // Ws: double-buffered 8x256
#define DIR_OFF (BS_OFF + 256)
#define SMEM_FLOATS (DIR_OFF + 384)
#define SMEM_BYTES  (SMEM_FLOATS * 4)   // 186,880 B

typedef unsigned long long ull;

__device__ __forceinline__ ull dup2(float v) {
    ull r; asm("mov.b64 %0, {%1, %1};" : "=l"(r) : "f"(v)); return r;
}
__device__ __forceinline__ void ffma2(ull &d, ull a, ull b) {
    asm("fma.rn.f32x2 %0, %1, %2, %0;" : "+l"(d) : "l"(a), "l"(b));
}
__device__ __forceinline__ float lo32(ull v) { return __uint_as_float((unsigned)v); }
__device__ __forceinline__ float hi32(ull v) { return __uint_as_float((unsigned)(v >> 32)); }

// One dense layer: out[128,256] = act(in cols) @ W[K,256] + b, optional ReLU,
// written in-place (feature-major) at column outoff. Double-buffered 8x256
// weight tiles. 512 threads: warp -> 8 rows, lane -> cols {4*lane..+3} and
// {128+4*lane..+3}; accumulators are f32x2 over row pairs.
__device__ __noinline__ void dense_layer(float* __restrict__ act,
                                         float* __restrict__ Ws,
                                         float* __restrict__ bs,
                                         const float* __restrict__ Wg,
                                         const float* __restrict__ bg,
                                         int K, int inoff, int outoff, int do_relu)
{
    const int tid  = threadIdx.x;
    const int lane = tid & 31;
    const int rw   = (tid >> 5) * 8;       // warp -> row base
    const int lk   = tid >> 6;             // 0..7 : k-row within weight tile
    const int ln   = (tid & 63) << 2;      // 0..252 : n-col within weight tile

    if (tid < 64) ((float4*)bs)[tid] = ((const float4*)bg)[tid];

    float4 wreg;
    {
        int kk = lk;
        if (kk < K) wreg = *(const float4*)(Wg + (size_t)kk * 256 + ln);
        else        wreg = make_float4(0.f, 0.f, 0.f, 0.f);
    }
    __syncthreads();   // prev-layer stores + bias visible; Ws buffers free

    ull acc[8][4];
    #pragma unroll
    for (int c = 0; c < 8; ++c) {
        int n = (c < 4) ? (lane * 4 + c) : (128 + lane * 4 + (c - 4));
        ull d = dup2(bs[n]);
        #pragma unroll
        for (int rp = 0; rp < 4; ++rp) acc[c][rp] = d;
    }

    *(float4*)(Ws + (size_t)lk * 256 + ln) = wreg;
    __syncthreads();

    const int nt = (K + 7) >> 3;
    for (int t = 0; t < nt; ++t) {
        if (t + 1 < nt) {
            int kk = (t + 1) * 8 + lk;
            if (kk < K) wreg = *(const float4*)(Wg + (size_t)kk * 256 + ln);
            else        wreg = make_float4(0.f, 0.f, 0.f, 0.f);
        }
        const float* wsb = Ws + (t & 1) * 2048;
        const int kbase = inoff + t * 8;
        #pragma unroll
        for (int k = 0; k < 8; ++k) {
            const float* ap = act + (size_t)(kbase + k) * AST + rw;   // warp-uniform: broadcast
            ulonglong2 aA = *(const ulonglong2*)ap;
            ulonglong2 aB = *(const ulonglong2*)(ap + 4);
            ull a2[4] = { aA.x, aA.y, aB.x, aB.y };
            const float* wp = wsb + k * 256 + (lane << 2);            // 16B/lane: conflict-free
            float4 b0 = *(const float4*)wp;
            float4 b1 = *(const float4*)(wp + 128);
            ull bd[8] = { dup2(b0.x), dup2(b0.y), dup2(b0.z), dup2(b0.w),
                          dup2(b1.x), dup2(b1.y), dup2(b1.z), dup2(b1.w) };
            #pragma unroll
            for (int c = 0; c < 8; ++c)
                #pragma unroll
                for (int rp = 0; rp < 4; ++rp)
                    ffma2(acc[c][rp], a2[rp], bd[c]);
        }
        __syncthreads();   // all reads of input cols + this buffer done
        if (t + 1 < nt) {
            *(float4*)(Ws + ((t + 1) & 1) * 2048 + (size_t)lk * 256 + ln) = wreg;
            __syncthreads();
        }
    }

    // Epilogue: ReLU + in-place store (safe: all input reads completed at the
    // unconditional sync of the final tile).
    #pragma unroll
    for (int c = 0; c < 8; ++c) {
        int n = (c < 4) ? (lane * 4 + c) : (128 + lane * 4 + (c - 4));
        float* op = act + (size_t)(outoff + n) * AST + rw;
        #pragma unroll
        for (int rp = 0; rp < 4; ++rp) {
            float lo = lo32(acc[c][rp]);
            float hi = hi32(acc[c][rp]);
            if (do_relu) { lo = fmaxf(lo, 0.f); hi = fmaxf(hi, 0.f); }
            op[2 * rp]     = lo;
            op[2 * rp + 1] = hi;
        }
    }
    // no trailing sync: next layer's entry sync covers visibility
}

__global__ void __launch_bounds__(TPB, 1) nerf_kernel(
    const float* __restrict__ x, const float* __restrict__ dirg,
    const float* g1_0_W, const float* g1_0_b,
    const float* g1_1_W, const float* g1_1_b,
    const float* g1_2_W, const float* g1_2_b,
    const float* g1_3_W, const float* g1_3_b,
    const float* g1_4_W, const float* g1_4_b,
    const float* g2_0_W, const float* g2_0_b,
    const float* g2_1_W, const float* g2_1_b,
    const float* g2_2_W, const float* g2_2_b,
    const float* c_0_W,  const float* c_0_b,
    const float* c_1_W,  const float* c_1_b,
    const float* sig_W,  const float* sig_b,
    float* __restrict__ out)
{
    extern __shared__ float smem[];
    float* act  = smem;
    float* Ws   = smem + WS_OFF;
    float* bs   = smem + BS_OFF;
    float* dirb = smem + DIR_OFF;

    const int tid  = threadIdx.x;
    const int row0 = blockIdx.x * MROWS;
    const int r = tid >> 2, p = tid & 3;

    // Zero the activation buffer (tail columns + first-layer tail reads rely on it)
    for (int i = tid; i < ACOLS * AST; i += TPB) act[i] = 0.f;

    // Load x / direction rows (4 threads per row)
    const float* xr = x + (size_t)(row0 + r) * 3;
    float xv0 = xr[0], xv1 = xr[1], xv2 = xr[2];
    if (p == 1) {
        const float* dr = dirg + (size_t)(row0 + r) * 3;
        dirb[r] = dr[0]; dirb[128 + r] = dr[1]; dirb[256 + r] = dr[2];
    }
    __syncthreads();   // zeros visible before PE writes

    // pe_x -> cols [0,63): [x, sin/cos interleaved per freq]
    if (p == 0) {
        act[0 * AST + r] = xv0; act[1 * AST + r] = xv1; act[2 * AST + r] = xv2;
    }
    for (int l = p; l < 10; l += 4) {
        float f = (float)(1 << l);
        float s, c;
        sincosf(xv0 * f, &s, &c); act[(3 + 6 * l + 0) * AST + r] = s; act[(6 + 6 * l + 0) * AST + r] = c;
        sincosf(xv1 * f, &s, &c); act[(3 + 6 * l + 1) * AST + r] = s; act[(6 + 6 * l + 1) * AST + r] = c;
        sincosf(xv2 * f, &s, &c); act[(3 + 6 * l + 2) * AST + r] = s; act[(6 + 6 * l + 2) * AST + r] = c;
    }

    // g1: 63->256, 256->256 x3 (ReLU), 256->256 (no ReLU)
    dense_layer(act, Ws, bs, g1_0_W, g1_0_b,  63,  0, 63, 1);
    dense_layer(act, Ws, bs, g1_1_W, g1_1_b, 256, 63, 63, 1);
    dense_layer(act, Ws, bs, g1_2_W, g1_2_b, 256, 63, 63, 1);
    dense_layer(act, Ws, bs, g1_3_W, g1_3_b, 256, 63, 63, 1);
    dense_layer(act, Ws, bs, g1_4_W, g1_4_b, 256, 63, 63, 0);

    // g2 layer0 reads cols [0,319) = [pe_x | features1]
    dense_layer(act, Ws, bs, g2_0_W, g2_0_b, 319,  0, 63, 1);

    // pe_d -> cols [24,63) (pe_x no longer needed). Safe: g2_0's final
    // internal sync ordered all reads of cols [0,63) before we get here.
    {
        float d0 = dirb[r], d1 = dirb[128 + r], d2 = dirb[256 + r];
        if (p == 0) {
            act[(24 + 0) * AST + r] = d0; act[(24 + 1) * AST + r] = d1; act[(24 + 2) * AST + r] = d2;
        }
        for (int l = p; l < 6; l += 4) {
            float f = (float)(1 << l);
            float s, c;
            sincosf(d0 * f, &s, &c); act[(27 + 6 * l + 0) * AST + r] = s; act[(30 + 6 * l + 0) * AST + r] = c;
            sincosf(d1 * f, &s, &c); act[(27 + 6 * l + 1) * AST + r] = s; act[(30 + 6 * l + 1) * AST + r] = c;
            sincosf(d2 * f, &s, &c); act[(27 + 6 * l + 2) * AST + r] = s; act[(30 + 6 * l + 2) * AST + r] = c;
        }
    }

    dense_layer(act, Ws, bs, g2_1_W, g2_1_b, 256, 63, 63, 1);
    dense_layer(act, Ws, bs, g2_2_W, g2_2_b, 256, 63, 63, 0);   // features2
    __syncthreads();

    // sigma = features2 @ sig_W + sig_b  (4 threads/row, shuffle reduce)
    float sigma_r;
    {
        float s = 0.f;
        #pragma unroll 8
        for (int kk = 0; kk < 64; ++kk) {
            int k = p * 64 + kk;
            s += act[(63 + k) * AST + r] * sig_W[k];
        }
        s += __shfl_xor_sync(0xffffffffu, s, 1);
        s += __shfl_xor_sync(0xffffffffu, s, 2);
        sigma_r = s + sig_b[0];
    }

    // color layer0 reads cols [24,319) = [pe_d | features2]; its entry sync
    // orders all sigma reads of features2 before the in-place overwrite.
    dense_layer(act, Ws, bs, c_0_W, c_0_b, 295, 24, 63, 1);
    __syncthreads();

    // color layer1: 256->3 (no ReLU) + fused output write [rgb, sigma]
    {
        float o0 = 0.f, o1 = 0.f, o2 = 0.f;
        #pragma unroll 8
        for (int kk = 0; kk < 64; ++kk) {
            int k = p * 64 + kk;
            float a = act[(63 + k) * AST + r];
            o0 += a * c_1_W[k * 3 + 0];
            o1 += a * c_1_W[k * 3 + 1];
            o2 += a * c_1_W[k * 3 + 2];
        }
        o0 += __shfl_xor_sync(0xffffffffu, o0, 1);
        o0 += __shfl_xor_sync(0xffffffffu, o0, 2);
        o1 += __shfl_xor_sync(0xffffffffu, o1, 1);
        o1 += __shfl_xor_sync(0xffffffffu, o1, 2);
        o2 += __shfl_xor_sync(0xffffffffu, o2, 1);
        o2 += __shfl_xor_sync(0xffffffffu, o2, 2);
        if (p == 0) {
            float4 o = make_float4(o0 + c_1_b[0], o1 + c_1_b[1], o2 + c_1_b[2], sigma_r);
            *(float4*)(out + (size_t)(row0 + r) * 4) = o;
        }
    }
}

extern "C" void kernel_launch(void* const* d_in, const int* in_sizes, int n_in,
                              void* d_out, int out_size)
{
    const float* x     = (const float*)d_in[0];
    const float* dirg  = (const float*)d_in[1];
    const float* g1_0_W = (const float*)d_in[2];  const float* g1_0_b = (const float*)d_in[3];
    const float* g1_1_W = (const float*)d_in[4];  const float* g1_1_b = (const float*)d_in[5];
    const float* g1_2_W = (const float*)d_in[6];  const float* g1_2_b = (const float*)d_in[7];
    const float* g1_3_W = (const float*)d_in[8];  const float* g1_3_b = (const float*)d_in[9];
    const float* g1_4_W = (const float*)d_in[10]; const float* g1_4_b = (const float*)d_in[11];
    const float* g2_0_W = (const float*)d_in[12]; const float* g2_0_b = (const float*)d_in[13];
    const float* g2_1_W = (const float*)d_in[14]; const float* g2_1_b = (const float*)d_in[15];
    const float* g2_2_W = (const float*)d_in[16]; const float* g2_2_b = (const float*)d_in[17];
    const float* c_0_W  = (const float*)d_in[18]; const float* c_0_b  = (const float*)d_in[19];
    const float* c_1_W  = (const float*)d_in[20]; const float* c_1_b  = (const float*)d_in[21];
    const float* sig_W  = (const float*)d_in[22]; const float* sig_b  = (const float*)d_in[23];
    float* out = (float*)d_out;

    const int N = in_sizes[0] / 3;           // 262144
    const int nblocks = N / MROWS;           // 2048

    cudaFuncSetAttribute(nerf_kernel, cudaFuncAttributeMaxDynamicSharedMemorySize, SMEM_BYTES);

    nerf_kernel<<<nblocks, TPB, SMEM_BYTES>>>(
        x, dirg,
        g1_0_W, g1_0_b, g1_1_W, g1_1_b, g1_2_W, g1_2_b, g1_3_W, g1_3_b, g1_4_W, g1_4_b,
        g2_0_W, g2_0_b, g2_1_W, g2_1_b, g2_2_W, g2_2_b,
        c_0_W, c_0_b, c_1_W, c_1_b,
        sig_W, sig_b,
        out);
}

// round 9
// speedup vs baseline: 4.2714x; 4.2714x over previous
#include <cuda_runtime.h>
#include <cuda_bf16.h>
#include <cstdint>

// ============================================================================
// NeRF fused MLP on tcgen05 (bf16 2-term split, fp32 TMEM accumulate).
// Prepass: W^T split to bf16 hi/lo, pre-swizzled SW128 blocked-atom images in
// a __device__ scratch buffer (per layer, per 64-K chunk: 32KB hi + 32KB lo).
// Main: per layer, per chunk: copy B chunk -> SMEM, 12 MMAs (4 K16-steps x
// {hh,hl,lh}), mbarrier wait; epilogue: LDTM f32 + bias + ReLU, re-split to
// the bf16 hi/lo A tiles in SMEM.
// A tile (per split): 128 rows x 320 K-cols, 64-col chunks of 16 KB:
//   cols [0,63) pe_x (later [24,63) = pe_d), col 63 zero, [64,320) features.
//
// tcgen05 is an arch-SPECIFIC (sm_103a) feature set. The harness's nvcc also
// emits a generic compute_103 PTX variant; tcgen05 asm must not appear there.
// All tcgen05 asm is guarded by HAS_TC; the generic variant gets no-ops and
// is never executed (driver picks the exact sm_103a SASS).
// ============================================================================

#if defined(__CUDA_ARCH_FEAT_SM103_ALL) || defined(__CUDA_ARCH_FEAT_SM100_ALL) || defined(__CUDA_ARCH_FEAT_SM101_ALL)
#define HAS_TC 1
#else
#define HAS_TC 0
#endif

#define TPB        512
#define MROWS      128
#define AHI_OFF    0
#define ALO_OFF    81920
#define B_OFF      163840
#define TMEMP_OFF  229376
#define MBAR_OFF   229384
#define SMEM_BYTES 229408
#define D1         0
#define D2         256
// idesc kind::f16: dtype=F32(1<<4), a=BF16(1<<7), b=BF16(1<<10), N=256, M=128
#define IDESC      0x8400490u

#define L0_OFF 0u
#define L1_OFF 65536u
#define L2_OFF 327680u
#define L3_OFF 589824u
#define L4_OFF 851968u
#define L5_OFF 1114112u
#define L6_OFF 1441792u
#define L7_OFF 1703936u
#define L8_OFF 1966080u
#define WSCRATCH_BYTES 2293760u

__device__ __align__(16) unsigned char g_wscratch[WSCRATCH_BYTES];

static __device__ __forceinline__ uint32_t swz(uint32_t b) { return b ^ ((b >> 3) & 0x70); }
static __device__ __forceinline__ uint32_t tile_off(int r, int k) {
    return (uint32_t)(((k >> 6) * 16 + (r >> 3)) * 1024)
         + swz((uint32_t)(((r & 7) << 7) | ((k & 63) << 1)));
}
static __device__ __forceinline__ uint32_t b_off(int n, int k) {
    return (uint32_t)((n >> 3) * 1024)
         + swz((uint32_t)(((n & 7) << 7) | ((k & 63) << 1)));
}
static __device__ __forceinline__ uint32_t smem_u32(const void* p) {
    uint32_t a;
    asm("{ .reg .u64 t; cvta.to.shared.u64 t, %1; cvt.u32.u64 %0, t; }" : "=r"(a) : "l"(p));
    return a;
}
static __device__ __forceinline__ uint32_t elect1() {
    uint32_t p;
    asm volatile("{ .reg .pred p; elect.sync _|p, 0xFFFFFFFF; selp.b32 %0, 1, 0, p; }" : "=r"(p));
    return p;
}
static __device__ __forceinline__ uint64_t mkdesc(uint32_t addr) {
    const uint64_t base = (uint64_t(2) << 61) | (uint64_t(1) << 46)
                        | (uint64_t(64) << 32) | (uint64_t(1) << 16);
    return base | ((uint64_t)(addr >> 4) & 0x3FFF);
}

static __device__ __forceinline__ void mma_ss(uint32_t d, uint64_t ad, uint64_t bd, uint32_t en) {
#if HAS_TC
    asm volatile(
        "{ .reg .pred p; setp.ne.u32 p, %5, 0;\n\t"
        "tcgen05.mma.cta_group::1.kind::f16 [%0], %1, %2, %3, {%4,%4,%4,%4}, p; }"
        :: "r"(d), "l"(ad), "l"(bd), "r"(IDESC), "r"(0u), "r"(en) : "memory");
#endif
}
static __device__ __forceinline__ void mbar_init(uint32_t a, uint32_t cnt) {
    asm volatile("mbarrier.init.shared.b64 [%0], %1;" :: "r"(a), "r"(cnt) : "memory");
}
static __device__ __forceinline__ void mbar_wait(uint32_t a, uint32_t parity) {
    uint32_t done;
    asm volatile(
        "{ .reg .pred p; mbarrier.try_wait.parity.acquire.cta.shared::cta.b64 p, [%1], %2;"
        " selp.b32 %0, 1, 0, p; }" : "=r"(done) : "r"(a), "r"(parity) : "memory");
    if (!done) {
        asm volatile(
            "{ .reg .pred P1;\n\t"
            "WL%=:\n\t"
            "mbarrier.try_wait.parity.acquire.cta.shared::cta.b64 P1, [%0], %1, 0x989680;\n\t"
            "@P1 bra WD%=;\n\t"
            "bra WL%=;\n\t"
            "WD%=:\n\t}" :: "r"(a), "r"(parity) : "memory");
    }
}

#if HAS_TC
#define TC_ALLOC(sa, n)   asm volatile("tcgen05.alloc.cta_group::1.sync.aligned.shared::cta.b32 [%0], %1;" :: "r"(sa), "r"(n) : "memory")
#define TC_RELINQ()       asm volatile("tcgen05.relinquish_alloc_permit.cta_group::1.sync.aligned;")
#define TC_DEALLOC(t, n)  asm volatile("tcgen05.dealloc.cta_group::1.sync.aligned.b32 %0, %1;" :: "r"(t), "r"(n))
#define TC_COMMIT(mb)     asm volatile("tcgen05.commit.cta_group::1.mbarrier::arrive::one.shared::cluster.b64 [%0];" :: "r"(mb) : "memory")
#define TC_FENCE_AFTER()  asm volatile("tcgen05.fence::after_thread_sync;" ::: "memory")
#define TC_FENCE_BEFORE() asm volatile("tcgen05.fence::before_thread_sync;" ::: "memory")
#define TC_WAIT_LD()      asm volatile("tcgen05.wait::ld.sync.aligned;" ::: "memory")
#define TC_LD_X32(r, ta) \
    asm volatile( \
        "tcgen05.ld.sync.aligned.32x32b.x32.b32 " \
        "{%0, %1, %2, %3, %4, %5, %6, %7, " \
        " %8, %9, %10, %11, %12, %13, %14, %15, " \
        " %16, %17, %18, %19, %20, %21, %22, %23, " \
        " %24, %25, %26, %27, %28, %29, %30, %31}, [%32];" \
        : "=r"((r)[0]),  "=r"((r)[1]),  "=r"((r)[2]),  "=r"((r)[3]), \
          "=r"((r)[4]),  "=r"((r)[5]),  "=r"((r)[6]),  "=r"((r)[7]), \
          "=r"((r)[8]),  "=r"((r)[9]),  "=r"((r)[10]), "=r"((r)[11]), \
          "=r"((r)[12]), "=r"((r)[13]), "=r"((r)[14]), "=r"((r)[15]), \
          "=r"((r)[16]), "=r"((r)[17]), "=r"((r)[18]), "=r"((r)[19]), \
          "=r"((r)[20]), "=r"((r)[21]), "=r"((r)[22]), "=r"((r)[23]), \
          "=r"((r)[24]), "=r"((r)[25]), "=r"((r)[26]), "=r"((r)[27]), \
          "=r"((r)[28]), "=r"((r)[29]), "=r"((r)[30]), "=r"((r)[31]) \
        : "r"(ta))
#else
#define TC_ALLOC(sa, n)   ((void)0)
#define TC_RELINQ()       ((void)0)
#define TC_DEALLOC(t, n)  ((void)0)
#define TC_COMMIT(mb)     ((void)0)
#define TC_FENCE_AFTER()  ((void)0)
#define TC_FENCE_BEFORE() ((void)0)
#define TC_WAIT_LD()      ((void)0)
#define TC_LD_X32(r, ta)  do { _Pragma("unroll") for (int _i = 0; _i < 32; ++_i) (r)[_i] = 0u; } while (0)
#endif
#define FENCE_ASYNC()     asm volatile("fence.proxy.async.shared::cta;" ::: "memory")

static __device__ __forceinline__ void a_store(char* Ahi, char* Alo, int r, int k, float v) {
    __nv_bfloat16 h = __float2bfloat16(v);
    float l = v - __bfloat162float(h);
    uint32_t o = tile_off(r, k);
    *(__nv_bfloat16*)(Ahi + o) = h;
    *(__nv_bfloat16*)(Alo + o) = __float2bfloat16(l);
}

// -------------------------------------------------------------- prepass -----
__global__ void nerf_prepass(
    const float* W0, const float* W1, const float* W2, const float* W3, const float* W4,
    const float* W5, const float* W6, const float* W7, const float* W8)
{
    int layer = blockIdx.y;
    int k = blockIdx.x;
    int n = threadIdx.x;
    const float* W; int Kpad, kaoff, kalen, kblen; uint32_t loff;
    switch (layer) {
        case 0: W = W0; Kpad = 64;  kaoff = 0;  kalen = 63;  kblen = 0;   loff = L0_OFF; break;
        case 1: W = W1; Kpad = 256; kaoff = 0;  kalen = 256; kblen = 0;   loff = L1_OFF; break;
        case 2: W = W2; Kpad = 256; kaoff = 0;  kalen = 256; kblen = 0;   loff = L2_OFF; break;
        case 3: W = W3; Kpad = 256; kaoff = 0;  kalen = 256; kblen = 0;   loff = L3_OFF; break;
        case 4: W = W4; Kpad = 256; kaoff = 0;  kalen = 256; kblen = 0;   loff = L4_OFF; break;
        case 5: W = W5; Kpad = 320; kaoff = 0;  kalen = 63;  kblen = 256; loff = L5_OFF; break;
        case 6: W = W6; Kpad = 256; kaoff = 0;  kalen = 256; kblen = 0;   loff = L6_OFF; break;
        case 7: W = W7; Kpad = 256; kaoff = 0;  kalen = 256; kblen = 0;   loff = L7_OFF; break;
        default: W = W8; Kpad = 320; kaoff = 24; kalen = 39; kblen = 256; loff = L8_OFF; break;
    }
    if (k >= Kpad) return;
    int row = -1;
    if (k >= kaoff && k < kaoff + kalen) row = k - kaoff;
    else if (kblen && k >= 64 && k < 64 + kblen) row = kalen + (k - 64);
    float v = (row >= 0) ? W[(size_t)row * 256 + n] : 0.f;

    uint32_t off = loff + (uint32_t)(k >> 6) * 65536u + b_off(n, k);
    __nv_bfloat16 h = __float2bfloat16(v);
    float l = v - __bfloat162float(h);
    *(__nv_bfloat16*)(g_wscratch + off)         = h;
    *(__nv_bfloat16*)(g_wscratch + off + 32768) = __float2bfloat16(l);
}

// ------------------------------------------------------------- run_layer ----
static __device__ __noinline__ void run_layer(
    char* smem, uint32_t sb, uint32_t tmem,
    uint32_t scratch_off, int nchunks, int a_chunk0, int d_off,
    const float* __restrict__ bias, int relu, int do_epi, int& par)
{
    const int tid = threadIdx.x;
    const uint64_t adh = mkdesc(sb + AHI_OFF);
    const uint64_t adl = mkdesc(sb + ALO_OFF);
    const uint64_t bdh = mkdesc(sb + B_OFF);
    const uint64_t bdl = mkdesc(sb + B_OFF + 32768);

    for (int c = 0; c < nchunks; ++c) {
        __syncthreads();
        const float4* __restrict__ src = (const float4*)(g_wscratch + scratch_off + (uint32_t)c * 65536u);
        float4* dst = (float4*)(smem + B_OFF);
        #pragma unroll 8
        for (int i = tid; i < 4096; i += TPB) dst[i] = src[i];
        __syncthreads();
        FENCE_ASYNC();
        if (tid < 32) {
            TC_FENCE_AFTER();
            if (elect1()) {
                #pragma unroll
                for (int j = 0; j < 4; ++j) {
                    uint64_t aoff = (uint64_t)(a_chunk0 + c) * 1024 + (uint64_t)j * 2;
                    mma_ss(tmem + d_off, adh + aoff, bdh + j * 2, (c > 0) || (j > 0));
                    mma_ss(tmem + d_off, adh + aoff, bdl + j * 2, 1u);
                    mma_ss(tmem + d_off, adl + aoff, bdh + j * 2, 1u);
                }
                TC_COMMIT(sb + MBAR_OFF);
            }
        }
        mbar_wait(sb + MBAR_OFF, (uint32_t)par);
        par ^= 1;
    }
    if (!do_epi) return;

    TC_FENCE_AFTER();
    const int w = tid >> 5, lane = tid & 31;
    const int r  = (w & 3) * 32 + lane;
    const int c0 = (w >> 2) * 64;
    char* Ahi = smem + AHI_OFF;
    char* Alo = smem + ALO_OFF;

    #pragma unroll
    for (int h = 0; h < 2; ++h) {
        uint32_t rg[32];
        TC_LD_X32(rg, tmem + d_off + c0 + h * 32);
        TC_WAIT_LD();
        const int kb = c0 + h * 32;
        #pragma unroll
        for (int q = 0; q < 4; ++q) {
            float4 b0 = __ldg((const float4*)(bias + kb + q * 8));
            float4 b1 = __ldg((const float4*)(bias + kb + q * 8 + 4));
            float v[8];
            v[0] = __uint_as_float(rg[q * 8 + 0]) + b0.x;
            v[1] = __uint_as_float(rg[q * 8 + 1]) + b0.y;
            v[2] = __uint_as_float(rg[q * 8 + 2]) + b0.z;
            v[3] = __uint_as_float(rg[q * 8 + 3]) + b0.w;
            v[4] = __uint_as_float(rg[q * 8 + 4]) + b1.x;
            v[5] = __uint_as_float(rg[q * 8 + 5]) + b1.y;
            v[6] = __uint_as_float(rg[q * 8 + 6]) + b1.z;
            v[7] = __uint_as_float(rg[q * 8 + 7]) + b1.w;
            if (relu) {
                #pragma unroll
                for (int e = 0; e < 8; ++e) v[e] = fmaxf(v[e], 0.f);
            }
            uint32_t hp[4], lp[4];
            #pragma unroll
            for (int e = 0; e < 4; ++e) {
                __nv_bfloat16 h0 = __float2bfloat16(v[2 * e]);
                __nv_bfloat16 h1 = __float2bfloat16(v[2 * e + 1]);
                float l0 = v[2 * e]     - __bfloat162float(h0);
                float l1 = v[2 * e + 1] - __bfloat162float(h1);
                __nv_bfloat16 g0 = __float2bfloat16(l0);
                __nv_bfloat16 g1 = __float2bfloat16(l1);
                hp[e] = (uint32_t)__bfloat16_as_ushort(h0) | ((uint32_t)__bfloat16_as_ushort(h1) << 16);
                lp[e] = (uint32_t)__bfloat16_as_ushort(g0) | ((uint32_t)__bfloat16_as_ushort(g1) << 16);
            }
            uint32_t off = tile_off(r, 64 + kb + q * 8);
            *(uint4*)(Ahi + off) = make_uint4(hp[0], hp[1], hp[2], hp[3]);
            *(uint4*)(Alo + off) = make_uint4(lp[0], lp[1], lp[2], lp[3]);
        }
    }
    TC_FENCE_BEFORE();
}

// ----------------------------------------------------------- main kernel ----
__global__ void __launch_bounds__(TPB, 1) nerf_main(
    const float* __restrict__ x, const float* __restrict__ dirg,
    const float* g1_0_b, const float* g1_1_b, const float* g1_2_b,
    const float* g1_3_b, const float* g1_4_b,
    const float* g2_0_b, const float* g2_1_b, const float* g2_2_b,
    const float* c_0_b,  const float* c_1_W,  const float* c_1_b,
    const float* sig_W,  const float* sig_b,
    float* __restrict__ out)
{
    extern __shared__ __align__(1024) char smem[];
    const uint32_t sb = smem_u32(smem);
    const int tid = threadIdx.x;
    const int w = tid >> 5, lane = tid & 31;
    char* Ahi = smem + AHI_OFF;
    char* Alo = smem + ALO_OFF;

    if (w == 0) { TC_ALLOC(sb + TMEMP_OFF, 512); TC_RELINQ(); }
    if (tid == 0) mbar_init(sb + MBAR_OFF, 1);
    __syncthreads();
    uint32_t tmem;
    asm volatile("ld.shared.b32 %0, [%1];" : "=r"(tmem) : "r"(sb + TMEMP_OFF));

    const int row0 = blockIdx.x * MROWS;
    const int r = tid >> 2, p = tid & 3;

    if (tid < 128) a_store(Ahi, Alo, tid, 63, 0.f);

    {
        const float* xr = x + (size_t)(row0 + r) * 3;
        float x0 = xr[0], x1 = xr[1], x2 = xr[2];
        if (p == 0) {
            a_store(Ahi, Alo, r, 0, x0);
            a_store(Ahi, Alo, r, 1, x1);
            a_store(Ahi, Alo, r, 2, x2);
        }
        for (int l = p; l < 10; l += 4) {
            float f = (float)(1 << l);
            float s, c;
            sincosf(x0 * f, &s, &c); a_store(Ahi, Alo, r, 3 + 6 * l + 0, s); a_store(Ahi, Alo, r, 6 + 6 * l + 0, c);
            sincosf(x1 * f, &s, &c); a_store(Ahi, Alo, r, 3 + 6 * l + 1, s); a_store(Ahi, Alo, r, 6 + 6 * l + 1, c);
            sincosf(x2 * f, &s, &c); a_store(Ahi, Alo, r, 3 + 6 * l + 2, s); a_store(Ahi, Alo, r, 6 + 6 * l + 2, c);
        }
    }

    int par = 0;
    run_layer(smem, sb, tmem, L0_OFF, 1, 0, D1, g1_0_b, 1, 1, par);
    run_layer(smem, sb, tmem, L1_OFF, 4, 1, D1, g1_1_b, 1, 1, par);
    run_layer(smem, sb, tmem, L2_OFF, 4, 1, D1, g1_2_b, 1, 1, par);
    run_layer(smem, sb, tmem, L3_OFF, 4, 1, D1, g1_3_b, 1, 1, par);
    run_layer(smem, sb, tmem, L4_OFF, 4, 1, D1, g1_4_b, 0, 1, par);
    run_layer(smem, sb, tmem, L5_OFF, 5, 0, D1, g2_0_b, 1, 1, par);

    // pe_d -> cols [24,63): safe, g2_0's MMAs (waited) consumed pe_x.
    {
        const float* dr = dirg + (size_t)(row0 + r) * 3;
        float d0 = dr[0], d1 = dr[1], d2 = dr[2];
        if (p == 0) {
            a_store(Ahi, Alo, r, 24, d0);
            a_store(Ahi, Alo, r, 25, d1);
            a_store(Ahi, Alo, r, 26, d2);
        }
        for (int l = p; l < 6; l += 4) {
            float f = (float)(1 << l);
            float s, c;
            sincosf(d0 * f, &s, &c); a_store(Ahi, Alo, r, 27 + 6 * l + 0, s); a_store(Ahi, Alo, r, 30 + 6 * l + 0, c);
            sincosf(d1 * f, &s, &c); a_store(Ahi, Alo, r, 27 + 6 * l + 1, s); a_store(Ahi, Alo, r, 30 + 6 * l + 1, c);
            sincosf(d2 * f, &s, &c); a_store(Ahi, Alo, r, 27 + 6 * l + 2, s); a_store(Ahi, Alo, r, 30 + 6 * l + 2, c);
        }
    }

    run_layer(smem, sb, tmem, L6_OFF, 4, 1, D1, g2_1_b, 1, 1, par);
    run_layer(smem, sb, tmem, L7_OFF, 4, 1, D2, g2_2_b, 0, 1, par);   // features2 -> D2 (preact)
    run_layer(smem, sb, tmem, L8_OFF, 5, 0, D1, c_0_b,  0, 0, par);   // c_0 preact -> D1
    TC_FENCE_AFTER();

    // stage head params into (now-idle) B region
    __syncthreads();
    float* SWM = (float*)(smem + B_OFF);
    for (int i = tid; i < 256; i += TPB) {
        SWM[i]        = sig_W[i];
        SWM[256 + i]  = c_0_b[i];
        SWM[1536 + i] = g2_2_b[i];
    }
    for (int i = tid; i < 768; i += TPB) SWM[512 + i] = c_1_W[i];
    if (tid == 0) {
        SWM[1280] = sig_b[0];
        SWM[1281] = c_1_b[0]; SWM[1282] = c_1_b[1]; SWM[1283] = c_1_b[2];
    }
    __syncthreads();

    // heads: sigma = (D2 + g2_2_b) . sig_W + sig_b ; rgb = relu(D1 + c_0_b) @ c_1
    if (w < 4) {
        const int rr = w * 32 + lane;
        float sig = 0.f;
        for (int blk = 0; blk < 8; ++blk) {
            uint32_t rg[32];
            TC_LD_X32(rg, tmem + D2 + blk * 32);
            TC_WAIT_LD();
            #pragma unroll
            for (int i = 0; i < 32; ++i) {
                int k = blk * 32 + i;
                sig += (__uint_as_float(rg[i]) + SWM[1536 + k]) * SWM[k];
            }
        }
        float o0 = 0.f, o1 = 0.f, o2 = 0.f;
        for (int blk = 0; blk < 8; ++blk) {
            uint32_t rg[32];
            TC_LD_X32(rg, tmem + D1 + blk * 32);
            TC_WAIT_LD();
            #pragma unroll
            for (int i = 0; i < 32; ++i) {
                int k = blk * 32 + i;
                float f = fmaxf(__uint_as_float(rg[i]) + SWM[256 + k], 0.f);
                o0 += f * SWM[512 + 3 * k + 0];
                o1 += f * SWM[512 + 3 * k + 1];
                o2 += f * SWM[512 + 3 * k + 2];
            }
        }
        float4 o = make_float4(o0 + SWM[1281], o1 + SWM[1282], o2 + SWM[1283], sig + SWM[1280]);
        *(float4*)(out + (size_t)(row0 + rr) * 4) = o;
        TC_FENCE_BEFORE();
    }
    __syncthreads();
    if (w == 0) TC_DEALLOC(tmem, 512);
}

// ---------------------------------------------------------------- launch ----
extern "C" void kernel_launch(void* const* d_in, const int* in_sizes, int n_in,
                              void* d_out, int out_size)
{
    const float* x      = (const float*)d_in[0];
    const float* dirg   = (const float*)d_in[1];
    const float* g1_0_W = (const float*)d_in[2];  const float* g1_0_b = (const float*)d_in[3];
    const float* g1_1_W = (const float*)d_in[4];  const float* g1_1_b = (const float*)d_in[5];
    const float* g1_2_W = (const float*)d_in[6];  const float* g1_2_b = (const float*)d_in[7];
    const float* g1_3_W = (const float*)d_in[8];  const float* g1_3_b = (const float*)d_in[9];
    const float* g1_4_W = (const float*)d_in[10]; const float* g1_4_b = (const float*)d_in[11];
    const float* g2_0_W = (const float*)d_in[12]; const float* g2_0_b = (const float*)d_in[13];
    const float* g2_1_W = (const float*)d_in[14]; const float* g2_1_b = (const float*)d_in[15];
    const float* g2_2_W = (const float*)d_in[16]; const float* g2_2_b = (const float*)d_in[17];
    const float* c_0_W  = (const float*)d_in[18]; const float* c_0_b  = (const float*)d_in[19];
    const float* c_1_W  = (const float*)d_in[20]; const float* c_1_b  = (const float*)d_in[21];
    const float* sig_W  = (const float*)d_in[22]; const float* sig_b  = (const float*)d_in[23];
    float* out = (float*)d_out;

    const int N = in_sizes[0] / 3;           // 262144
    const int nblocks = N / MROWS;           // 2048

    dim3 pgrid(320, 9);
    nerf_prepass<<<pgrid, 256>>>(g1_0_W, g1_1_W, g1_2_W, g1_3_W, g1_4_W,
                                 g2_0_W, g2_1_W, g2_2_W, c_0_W);

    cudaFuncSetAttribute(nerf_main, cudaFuncAttributeMaxDynamicSharedMemorySize, SMEM_BYTES);
    nerf_main<<<nblocks, TPB, SMEM_BYTES>>>(
        x, dirg,
        g1_0_b, g1_1_b, g1_2_b, g1_3_b, g1_4_b,
        g2_0_b, g2_1_b, g2_2_b,
        c_0_b, c_1_W, c_1_b,
        sig_W, sig_b,
        out);
}

// round 10
// speedup vs baseline: 5.4956x; 1.2866x over previous
#include <cuda_runtime.h>
#include <cuda_bf16.h>
#include <cstdint>

// ============================================================================
// NeRF fused MLP on tcgen05 (bf16 2-term split, fp32 TMEM accumulate),
// R10: async double-buffered weight pipeline.
//
// Prepass: W^T split to bf16 hi/lo, pre-swizzled SW128 images in __device__
// scratch. Chunk = 32 K-cols packed into ONE 32KB 64-col SW128 frame:
//   frame K-cols [0,32) = hi of K[32c..32c+32), [32,64) = lo of same.
// Main: 2x32KB SMEM B buffers. Warp0-elect control thread runs the pipeline:
//   wait full[buf] -> 6 MMAs (2 K16-steps x {hh,hl,lh}) -> commit ->
//   wait mma[buf] -> cp.async.bulk chunk c+2 into buf (spills into next
//   layer's chunks 0,1 => copies overlap the epilogue). Epilogue: LDTM f32 +
//   bias + ReLU, re-split to bf16 hi/lo A tiles.
// A tile (per split): 128 rows x 320 K-cols SW128 blocked atoms:
//   cols [0,63) pe_x (later [24,63)=pe_d), col 63 zero, [64,320) features.
//
// tcgen05 asm guarded by HAS_TC so the generic compute_103 PTX variant (never
// executed) contains none of it. cp.async.bulk/mbarrier are sm_90 baseline.
// ============================================================================

#if defined(__CUDA_ARCH_FEAT_SM103_ALL) || defined(__CUDA_ARCH_FEAT_SM100_ALL) || defined(__CUDA_ARCH_FEAT_SM101_ALL)
#define HAS_TC 1
#else
#define HAS_TC 0
#endif

#define TPB        512
#define MROWS      128
#define AHI_OFF    0
#define ALO_OFF    81920
#define B_OFF      163840            // 2 x 32KB buffers
#define TMEMP_OFF  229376
#define MBAR_OFF   229384            // full0, full1, mma0, mma1 (8B each)
#define SMEM_BYTES 229440
#define D1         0
#define D2         256
// idesc kind::f16: dtype=F32(1<<4), a=BF16(1<<7), b=BF16(1<<10), N=256, M=128
#define IDESC      0x8400490u

#define L0_OFF 0u
#define L1_OFF 65536u
#define L2_OFF 327680u
#define L3_OFF 589824u
#define L4_OFF 851968u
#define L5_OFF 1114112u
#define L6_OFF 1441792u
#define L7_OFF 1703936u
#define L8_OFF 1966080u
#define NO_NEXT 0xFFFFFFFFu
#define WSCRATCH_BYTES 2293760u

__device__ __align__(128) unsigned char g_wscratch[WSCRATCH_BYTES];

static __device__ __forceinline__ uint32_t swz(uint32_t b) { return b ^ ((b >> 3) & 0x70); }
static __device__ __forceinline__ uint32_t tile_off(int r, int k) {
    return (uint32_t)(((k >> 6) * 16 + (r >> 3)) * 1024)
         + swz((uint32_t)(((r & 7) << 7) | ((k & 63) << 1)));
}
static __device__ __forceinline__ uint32_t b_off(int n, int k) {
    return (uint32_t)((n >> 3) * 1024)
         + swz((uint32_t)(((n & 7) << 7) | ((k & 63) << 1)));
}
static __device__ __forceinline__ uint32_t smem_u32(const void* p) {
    uint32_t a;
    asm("{ .reg .u64 t; cvta.to.shared.u64 t, %1; cvt.u32.u64 %0, t; }" : "=r"(a) : "l"(p));
    return a;
}
static __device__ __forceinline__ uint32_t elect1() {
    uint32_t p;
    asm volatile("{ .reg .pred p; elect.sync _|p, 0xFFFFFFFF; selp.b32 %0, 1, 0, p; }" : "=r"(p));
    return p;
}
static __device__ __forceinline__ uint64_t mkdesc(uint32_t addr) {
    const uint64_t base = (uint64_t(2) << 61) | (uint64_t(1) << 46)
                        | (uint64_t(64) << 32) | (uint64_t(1) << 16);
    return base | ((uint64_t)(addr >> 4) & 0x3FFF);
}

static __device__ __forceinline__ void mma_ss(uint32_t d, uint64_t ad, uint64_t bd, uint32_t en) {
#if HAS_TC
    asm volatile(
        "{ .reg .pred p; setp.ne.u32 p, %5, 0;\n\t"
        "tcgen05.mma.cta_group::1.kind::f16 [%0], %1, %2, %3, {%4,%4,%4,%4}, p; }"
        :: "r"(d), "l"(ad), "l"(bd), "r"(IDESC), "r"(0u), "r"(en) : "memory");
#endif
}
static __device__ __forceinline__ void mbar_init(uint32_t a, uint32_t cnt) {
    asm volatile("mbarrier.init.shared.b64 [%0], %1;" :: "r"(a), "r"(cnt) : "memory");
}
static __device__ __forceinline__ void mbar_expect_tx(uint32_t a, uint32_t bytes) {
    asm volatile("mbarrier.arrive.expect_tx.shared.b64 _, [%0], %1;" :: "r"(a), "r"(bytes) : "memory");
}
static __device__ __forceinline__ void bulk_copy32k(uint32_t dst, const void* src, uint32_t mbar) {
    asm volatile(
        "cp.async.bulk.shared::cluster.global.mbarrier::complete_tx::bytes [%0], [%1], %2, [%3];"
        :: "r"(dst), "l"(src), "r"(32768u), "r"(mbar) : "memory");
}
static __device__ __forceinline__ void mbar_wait(uint32_t a, uint32_t parity) {
    uint32_t done;
    asm volatile(
        "{ .reg .pred p; mbarrier.try_wait.parity.acquire.cta.shared::cta.b64 p, [%1], %2;"
        " selp.b32 %0, 1, 0, p; }" : "=r"(done) : "r"(a), "r"(parity) : "memory");
    if (!done) {
        asm volatile(
            "{ .reg .pred P1;\n\t"
            "WL%=:\n\t"
            "mbarrier.try_wait.parity.acquire.cta.shared::cta.b64 P1, [%0], %1, 0x989680;\n\t"
            "@P1 bra WD%=;\n\t"
            "bra WL%=;\n\t"
            "WD%=:\n\t}" :: "r"(a), "r"(parity) : "memory");
    }
}

#if HAS_TC
#define TC_ALLOC(sa, n)   asm volatile("tcgen05.alloc.cta_group::1.sync.aligned.shared::cta.b32 [%0], %1;" :: "r"(sa), "r"(n) : "memory")
#define TC_RELINQ()       asm volatile("tcgen05.relinquish_alloc_permit.cta_group::1.sync.aligned;")
#define TC_DEALLOC(t, n)  asm volatile("tcgen05.dealloc.cta_group::1.sync.aligned.b32 %0, %1;" :: "r"(t), "r"(n))
#define TC_COMMIT(mb)     asm volatile("tcgen05.commit.cta_group::1.mbarrier::arrive::one.shared::cluster.b64 [%0];" :: "r"(mb) : "memory")
#define TC_FENCE_AFTER()  asm volatile("tcgen05.fence::after_thread_sync;" ::: "memory")
#define TC_FENCE_BEFORE() asm volatile("tcgen05.fence::before_thread_sync;" ::: "memory")
#define TC_WAIT_LD()      asm volatile("tcgen05.wait::ld.sync.aligned;" ::: "memory")
#define TC_LD_X32(r, ta) \
    asm volatile( \
        "tcgen05.ld.sync.aligned.32x32b.x32.b32 " \
        "{%0, %1, %2, %3, %4, %5, %6, %7, " \
        " %8, %9, %10, %11, %12, %13, %14, %15, " \
        " %16, %17, %18, %19, %20, %21, %22, %23, " \
        " %24, %25, %26, %27, %28, %29, %30, %31}, [%32];" \
        : "=r"((r)[0]),  "=r"((r)[1]),  "=r"((r)[2]),  "=r"((r)[3]), \
          "=r"((r)[4]),  "=r"((r)[5]),  "=r"((r)[6]),  "=r"((r)[7]), \
          "=r"((r)[8]),  "=r"((r)[9]),  "=r"((r)[10]), "=r"((r)[11]), \
          "=r"((r)[12]), "=r"((r)[13]), "=r"((r)[14]), "=r"((r)[15]), \
          "=r"((r)[16]), "=r"((r)[17]), "=r"((r)[18]), "=r"((r)[19]), \
          "=r"((r)[20]), "=r"((r)[21]), "=r"((r)[22]), "=r"((r)[23]), \
          "=r"((r)[24]), "=r"((r)[25]), "=r"((r)[26]), "=r"((r)[27]), \
          "=r"((r)[28]), "=r"((r)[29]), "=r"((r)[30]), "=r"((r)[31]) \
        : "r"(ta))
#else
#define TC_ALLOC(sa, n)   ((void)0)
#define TC_RELINQ()       ((void)0)
#define TC_DEALLOC(t, n)  ((void)0)
#define TC_COMMIT(mb)     ((void)0)
#define TC_FENCE_AFTER()  ((void)0)
#define TC_FENCE_BEFORE() ((void)0)
#define TC_WAIT_LD()      ((void)0)
#define TC_LD_X32(r, ta)  do { _Pragma("unroll") for (int _i = 0; _i < 32; ++_i) (r)[_i] = 0u; } while (0)
#endif
#define FENCE_ASYNC()     asm volatile("fence.proxy.async.shared::cta;" ::: "memory")

static __device__ __forceinline__ void a_store(char* Ahi, char* Alo, int r, int k, float v) {
    __nv_bfloat16 h = __float2bfloat16(v);
    float l = v - __bfloat162float(h);
    uint32_t o = tile_off(r, k);
    *(__nv_bfloat16*)(Ahi + o) = h;
    *(__nv_bfloat16*)(Alo + o) = __float2bfloat16(l);
}

// -------------------------------------------------------------- prepass -----
__global__ void nerf_prepass(
    const float* W0, const float* W1, const float* W2, const float* W3, const float* W4,
    const float* W5, const float* W6, const float* W7, const float* W8)
{
    int layer = blockIdx.y;
    int k = blockIdx.x;
    int n = threadIdx.x;
    const float* W; int Kpad, kaoff, kalen, kblen; uint32_t loff;
    switch (layer) {
        case 0: W = W0; Kpad = 64;  kaoff = 0;  kalen = 63;  kblen = 0;   loff = L0_OFF; break;
        case 1: W = W1; Kpad = 256; kaoff = 0;  kalen = 256; kblen = 0;   loff = L1_OFF; break;
        case 2: W = W2; Kpad = 256; kaoff = 0;  kalen = 256; kblen = 0;   loff = L2_OFF; break;
        case 3: W = W3; Kpad = 256; kaoff = 0;  kalen = 256; kblen = 0;   loff = L3_OFF; break;
        case 4: W = W4; Kpad = 256; kaoff = 0;  kalen = 256; kblen = 0;   loff = L4_OFF; break;
        case 5: W = W5; Kpad = 320; kaoff = 0;  kalen = 63;  kblen = 256; loff = L5_OFF; break;
        case 6: W = W6; Kpad = 256; kaoff = 0;  kalen = 256; kblen = 0;   loff = L6_OFF; break;
        case 7: W = W7; Kpad = 256; kaoff = 0;  kalen = 256; kblen = 0;   loff = L7_OFF; break;
        default: W = W8; Kpad = 320; kaoff = 24; kalen = 39; kblen = 256; loff = L8_OFF; break;
    }
    if (k >= Kpad) return;
    int row = -1;
    if (k >= kaoff && k < kaoff + kalen) row = k - kaoff;
    else if (kblen && k >= 64 && k < 64 + kblen) row = kalen + (k - 64);
    float v = (row >= 0) ? W[(size_t)row * 256 + n] : 0.f;

    // 32-K chunk frame: hi at local cols [0,32), lo at [32,64)
    uint32_t cbase = loff + (uint32_t)(k >> 5) * 32768u;
    int local = k & 31;
    __nv_bfloat16 h = __float2bfloat16(v);
    float l = v - __bfloat162float(h);
    *(__nv_bfloat16*)(g_wscratch + cbase + b_off(n, local))      = h;
    *(__nv_bfloat16*)(g_wscratch + cbase + b_off(n, 32 + local)) = __float2bfloat16(l);
}

// ------------------------------------------------------------- run_layer ----
struct Pipe { int pf0, pf1, pm0, pm1; };

static __device__ __noinline__ void run_layer(
    char* smem, uint32_t sb, uint32_t tmem,
    uint32_t scratch_off, int nch, int a_units0, int d_off,
    const float* __restrict__ bias, int relu, int do_epi,
    uint32_t next_scratch, Pipe& pp)
{
    const int tid = threadIdx.x;
    const int w = tid >> 5;
    __syncthreads();   // A writes (PE / prev epilogue, each fenced) before MMA issue

    if (w == 0 && elect1()) {
        const uint64_t adh = mkdesc(sb + AHI_OFF);
        const uint64_t adl = mkdesc(sb + ALO_OFF);
        for (int c = 0; c < nch; ++c) {
            const int buf = c & 1;
            const uint32_t fm = sb + MBAR_OFF + (uint32_t)buf * 8u;
            const uint32_t mm = sb + MBAR_OFF + 16u + (uint32_t)buf * 8u;
            int& pf = buf ? pp.pf1 : pp.pf0;
            int& pm = buf ? pp.pm1 : pp.pm0;

            mbar_wait(fm, (uint32_t)pf); pf ^= 1;        // copy of chunk c done
            const uint64_t bd = mkdesc(sb + B_OFF + (uint32_t)buf * 32768u);
            #pragma unroll
            for (int j = 0; j < 2; ++j) {
                int s = 2 * c + j;
                uint64_t aoff = (uint64_t)(a_units0 + (s >> 2) * 1024 + (s & 3) * 2);
                mma_ss(tmem + d_off, adh + aoff, bd + 2 * j,     (c > 0) || (j > 0));
                mma_ss(tmem + d_off, adh + aoff, bd + 4 + 2 * j, 1u);
                mma_ss(tmem + d_off, adl + aoff, bd + 2 * j,     1u);
            }
            TC_COMMIT(mm);
            mbar_wait(mm, (uint32_t)pm); pm ^= 1;        // chunk c MMAs done -> buffer free
            // schedule copy of logical chunk c+2 into this buffer (may spill
            // into the next layer's chunks 0,1 -> overlaps the epilogue)
            int t = c + 2;
            const unsigned char* src = 0;
            if (t < nch) src = g_wscratch + scratch_off + (uint32_t)t * 32768u;
            else if (next_scratch != NO_NEXT && t - nch < 2)
                src = g_wscratch + next_scratch + (uint32_t)(t - nch) * 32768u;
            if (src) {
                mbar_expect_tx(fm, 32768u);
                bulk_copy32k(sb + B_OFF + (uint32_t)buf * 32768u, src, fm);
            }
        }
    }
    if (!do_epi) return;

    __syncthreads();   // control loop done: all layer MMAs complete
    TC_FENCE_AFTER();
    const int lane = tid & 31;
    const int r  = (w & 3) * 32 + lane;
    const int c0 = (w >> 2) * 64;
    char* Ahi = smem + AHI_OFF;
    char* Alo = smem + ALO_OFF;

    #pragma unroll
    for (int h = 0; h < 2; ++h) {
        uint32_t rg[32];
        TC_LD_X32(rg, tmem + d_off + c0 + h * 32);
        TC_WAIT_LD();
        const int kb = c0 + h * 32;
        #pragma unroll
        for (int q = 0; q < 4; ++q) {
            float4 b0 = __ldg((const float4*)(bias + kb + q * 8));
            float4 b1 = __ldg((const float4*)(bias + kb + q * 8 + 4));
            float v[8];
            v[0] = __uint_as_float(rg[q * 8 + 0]) + b0.x;
            v[1] = __uint_as_float(rg[q * 8 + 1]) + b0.y;
            v[2] = __uint_as_float(rg[q * 8 + 2]) + b0.z;
            v[3] = __uint_as_float(rg[q * 8 + 3]) + b0.w;
            v[4] = __uint_as_float(rg[q * 8 + 4]) + b1.x;
            v[5] = __uint_as_float(rg[q * 8 + 5]) + b1.y;
            v[6] = __uint_as_float(rg[q * 8 + 6]) + b1.z;
            v[7] = __uint_as_float(rg[q * 8 + 7]) + b1.w;
            if (relu) {
                #pragma unroll
                for (int e = 0; e < 8; ++e) v[e] = fmaxf(v[e], 0.f);
            }
            uint32_t hp[4], lp[4];
            #pragma unroll
            for (int e = 0; e < 4; ++e) {
                __nv_bfloat16 h0 = __float2bfloat16(v[2 * e]);
                __nv_bfloat16 h1 = __float2bfloat16(v[2 * e + 1]);
                float l0 = v[2 * e]     - __bfloat162float(h0);
                float l1 = v[2 * e + 1] - __bfloat162float(h1);
                __nv_bfloat16 g0 = __float2bfloat16(l0);
                __nv_bfloat16 g1 = __float2bfloat16(l1);
                hp[e] = (uint32_t)__bfloat16_as_ushort(h0) | ((uint32_t)__bfloat16_as_ushort(h1) << 16);
                lp[e] = (uint32_t)__bfloat16_as_ushort(g0) | ((uint32_t)__bfloat16_as_ushort(g1) << 16);
            }
            uint32_t off = tile_off(r, 64 + kb + q * 8);
            *(uint4*)(Ahi + off) = make_uint4(hp[0], hp[1], hp[2], hp[3]);
            *(uint4*)(Alo + off) = make_uint4(lp[0], lp[1], lp[2], lp[3]);
        }
    }
    TC_FENCE_BEFORE();
    FENCE_ASYNC();     // A writes visible to async proxy before next layer's MMAs
}

// ----------------------------------------------------------- main kernel ----
__global__ void __launch_bounds__(TPB, 1) nerf_main(
    const float* __restrict__ x, const float* __restrict__ dirg,
    const float* g1_0_b, const float* g1_1_b, const float* g1_2_b,
    const float* g1_3_b, const float* g1_4_b,
    const float* g2_0_b, const float* g2_1_b, const float* g2_2_b,
    const float* c_0_b,  const float* c_1_W,  const float* c_1_b,
    const float* sig_W,  const float* sig_b,
    float* __restrict__ out)
{
    extern __shared__ __align__(1024) char smem[];
    const uint32_t sb = smem_u32(smem);
    const int tid = threadIdx.x;
    const int w = tid >> 5, lane = tid & 31;
    char* Ahi = smem + AHI_OFF;
    char* Alo = smem + ALO_OFF;

    if (w == 0) { TC_ALLOC(sb + TMEMP_OFF, 512); TC_RELINQ(); }
    if (w == 0 && elect1()) {
        mbar_init(sb + MBAR_OFF + 0,  1);   // full0
        mbar_init(sb + MBAR_OFF + 8,  1);   // full1
        mbar_init(sb + MBAR_OFF + 16, 1);   // mma0
        mbar_init(sb + MBAR_OFF + 24, 1);   // mma1
        FENCE_ASYNC();
        // prologue: L0 chunks 0,1 in flight during PE computation
        mbar_expect_tx(sb + MBAR_OFF + 0, 32768u);
        bulk_copy32k(sb + B_OFF,          g_wscratch + L0_OFF,          sb + MBAR_OFF + 0);
        mbar_expect_tx(sb + MBAR_OFF + 8, 32768u);
        bulk_copy32k(sb + B_OFF + 32768u, g_wscratch + L0_OFF + 32768u, sb + MBAR_OFF + 8);
    }
    __syncthreads();
    uint32_t tmem;
    asm volatile("ld.shared.b32 %0, [%1];" : "=r"(tmem) : "r"(sb + TMEMP_OFF));

    const int row0 = blockIdx.x * MROWS;
    const int r = tid >> 2, p = tid & 3;

    if (tid < 128) a_store(Ahi, Alo, tid, 63, 0.f);

    {
        const float* xr = x + (size_t)(row0 + r) * 3;
        float x0 = xr[0], x1 = xr[1], x2 = xr[2];
        if (p == 0) {
            a_store(Ahi, Alo, r, 0, x0);
            a_store(Ahi, Alo, r, 1, x1);
            a_store(Ahi, Alo, r, 2, x2);
        }
        for (int l = p; l < 10; l += 4) {
            float f = (float)(1 << l);
            float s, c;
            sincosf(x0 * f, &s, &c); a_store(Ahi, Alo, r, 3 + 6 * l + 0, s); a_store(Ahi, Alo, r, 6 + 6 * l + 0, c);
            sincosf(x1 * f, &s, &c); a_store(Ahi, Alo, r, 3 + 6 * l + 1, s); a_store(Ahi, Alo, r, 6 + 6 * l + 1, c);
            sincosf(x2 * f, &s, &c); a_store(Ahi, Alo, r, 3 + 6 * l + 2, s); a_store(Ahi, Alo, r, 6 + 6 * l + 2, c);
        }
    }
    FENCE_ASYNC();

    Pipe pp = {0, 0, 0, 0};
    run_layer(smem, sb, tmem, L0_OFF,  2, 0,    D1, g1_0_b, 1, 1, L1_OFF, pp);
    run_layer(smem, sb, tmem, L1_OFF,  8, 1024, D1, g1_1_b, 1, 1, L2_OFF, pp);
    run_layer(smem, sb, tmem, L2_OFF,  8, 1024, D1, g1_2_b, 1, 1, L3_OFF, pp);
    run_layer(smem, sb, tmem, L3_OFF,  8, 1024, D1, g1_3_b, 1, 1, L4_OFF, pp);
    run_layer(smem, sb, tmem, L4_OFF,  8, 1024, D1, g1_4_b, 0, 1, L5_OFF, pp);
    run_layer(smem, sb, tmem, L5_OFF, 10, 0,    D1, g2_0_b, 1, 1, L6_OFF, pp);

    // pe_d -> cols [24,63): safe, all of g2_0's MMAs were waited in-loop.
    {
        const float* dr = dirg + (size_t)(row0 + r) * 3;
        float d0 = dr[0], d1 = dr[1], d2 = dr[2];
        if (p == 0) {
            a_store(Ahi, Alo, r, 24, d0);
            a_store(Ahi, Alo, r, 25, d1);
            a_store(Ahi, Alo, r, 26, d2);
        }
        for (int l = p; l < 6; l += 4) {
            float f = (float)(1 << l);
            float s, c;
            sincosf(d0 * f, &s, &c); a_store(Ahi, Alo, r, 27 + 6 * l + 0, s); a_store(Ahi, Alo, r, 30 + 6 * l + 0, c);
            sincosf(d1 * f, &s, &c); a_store(Ahi, Alo, r, 27 + 6 * l + 1, s); a_store(Ahi, Alo, r, 30 + 6 * l + 1, c);
            sincosf(d2 * f, &s, &c); a_store(Ahi, Alo, r, 27 + 6 * l + 2, s); a_store(Ahi, Alo, r, 30 + 6 * l + 2, c);
        }
        FENCE_ASYNC();
    }

    run_layer(smem, sb, tmem, L6_OFF,  8, 1024, D1, g2_1_b, 1, 1, L7_OFF, pp);
    run_layer(smem, sb, tmem, L7_OFF,  8, 1024, D2, g2_2_b, 0, 1, L8_OFF, pp);   // features2 -> D2
    run_layer(smem, sb, tmem, L8_OFF, 10, 0,    D1, c_0_b,  0, 0, NO_NEXT, pp);  // c_0 preact -> D1

    __syncthreads();   // control loop of L8 done: all MMAs complete
    TC_FENCE_AFTER();

    // stage head params into (now-idle) B region
    float* SWM = (float*)(smem + B_OFF);
    for (int i = tid; i < 256; i += TPB) {
        SWM[i]        = sig_W[i];
        SWM[256 + i]  = c_0_b[i];
        SWM[1536 + i] = g2_2_b[i];
    }
    for (int i = tid; i < 768; i += TPB) SWM[512 + i] = c_1_W[i];
    if (tid == 0) {
        SWM[1280] = sig_b[0];
        SWM[1281] = c_1_b[0]; SWM[1282] = c_1_b[1]; SWM[1283] = c_1_b[2];
    }
    __syncthreads();

    // heads: sigma = (D2 + g2_2_b) . sig_W + sig_b ; rgb = relu(D1 + c_0_b) @ c_1
    if (w < 4) {
        const int rr = w * 32 + lane;
        float sig = 0.f;
        for (int blk = 0; blk < 8; ++blk) {
            uint32_t rg[32];
            TC_LD_X32(rg, tmem + D2 + blk * 32);
            TC_WAIT_LD();
            #pragma unroll
            for (int i = 0; i < 32; ++i) {
                int k = blk * 32 + i;
                sig += (__uint_as_float(rg[i]) + SWM[1536 + k]) * SWM[k];
            }
        }
        float o0 = 0.f, o1 = 0.f, o2 = 0.f;
        for (int blk = 0; blk < 8; ++blk) {
            uint32_t rg[32];
            TC_LD_X32(rg, tmem + D1 + blk * 32);
            TC_WAIT_LD();
            #pragma unroll
            for (int i = 0; i < 32; ++i) {
                int k = blk * 32 + i;
                float f = fmaxf(__uint_as_float(rg[i]) + SWM[256 + k], 0.f);
                o0 += f * SWM[512 + 3 * k + 0];
                o1 += f * SWM[512 + 3 * k + 1];
                o2 += f * SWM[512 + 3 * k + 2];
            }
        }
        float4 o = make_float4(o0 + SWM[1281], o1 + SWM[1282], o2 + SWM[1283], sig + SWM[1280]);
        *(float4*)(out + (size_t)(row0 + rr) * 4) = o;
        TC_FENCE_BEFORE();
    }
    __syncthreads();
    if (w == 0) TC_DEALLOC(tmem, 512);
}

// ---------------------------------------------------------------- launch ----
extern "C" void kernel_launch(void* const* d_in, const int* in_sizes, int n_in,
                              void* d_out, int out_size)
{
    const float* x      = (const float*)d_in[0];
    const float* dirg   = (const float*)d_in[1];
    const float* g1_0_W = (const float*)d_in[2];  const float* g1_0_b = (const float*)d_in[3];
    const float* g1_1_W = (const float*)d_in[4];  const float* g1_1_b = (const float*)d_in[5];
    const float* g1_2_W = (const float*)d_in[6];  const float* g1_2_b = (const float*)d_in[7];
    const float* g1_3_W = (const float*)d_in[8];  const float* g1_3_b = (const float*)d_in[9];
    const float* g1_4_W = (const float*)d_in[10]; const float* g1_4_b = (const float*)d_in[11];
    const float* g2_0_W = (const float*)d_in[12]; const float* g2_0_b = (const float*)d_in[13];
    const float* g2_1_W = (const float*)d_in[14]; const float* g2_1_b = (const float*)d_in[15];
    const float* g2_2_W = (const float*)d_in[16]; const float* g2_2_b = (const float*)d_in[17];
    const float* c_0_W  = (const float*)d_in[18]; const float* c_0_b  = (const float*)d_in[19];
    const float* c_1_W  = (const float*)d_in[20]; const float* c_1_b  = (const float*)d_in[21];
    const float* sig_W  = (const float*)d_in[22]; const float* sig_b  = (const float*)d_in[23];
    float* out = (float*)d_out;

    const int N = in_sizes[0] / 3;           // 262144
    const int nblocks = N / MROWS;           // 2048

    dim3 pgrid(320, 9);
    nerf_prepass<<<pgrid, 256>>>(g1_0_W, g1_1_W, g1_2_W, g1_3_W, g1_4_W,
                                 g2_0_W, g2_1_W, g2_2_W, c_0_W);

    cudaFuncSetAttribute(nerf_main, cudaFuncAttributeMaxDynamicSharedMemorySize, SMEM_BYTES);
    nerf_main<<<nblocks, TPB, SMEM_BYTES>>>(
        x, dirg,
        g1_0_b, g1_1_b, g1_2_b, g1_3_b, g1_4_b,
        g2_0_b, g2_1_b, g2_2_b,
        c_0_b, c_1_W, c_1_b,
        sig_W, sig_b,
        out);
}